// round 15
// baseline (speedup 1.0000x reference)
#include <cuda_runtime.h>
#include <cuda_fp16.h>
#include <cstdint>
#include <math.h>

// ---------------------------------------------------------------- constants
#define N_TOK 4096
#define IN_D  1024
#define OUT_D 1024
#define E_N   8
#define R_N   16
#define HG_N  256
#define ER_N  128

// scratch (no allocation allowed)
__device__ float  g_C[(size_t)N_TOK * ER_N];        // 2 MB coeffs (fp32, k_proj bx2)
__device__ __half g_C16[(size_t)N_TOK * ER_N];      // 1 MB coeffs fp16 (fused gate)
__device__ __half g_X16[(size_t)N_TOK * IN_D];      // 8 MB X fp16
__device__ __half g_Wmr16[(size_t)OUT_D * IN_D];    // 2 MB Wm fp16 (bx3 CTAs)
__device__ __half g_Ur16[(size_t)E_N * OUT_D * R_N];// 256 KB U fp16 (bx3 CTAs)
__device__ __half g_Vr16[(size_t)E_N * R_N * IN_D]; // 256 KB V fp16
__device__ __half g_Wg1T16[(size_t)HG_N * IN_D];    // 512 KB Wg1^T fp16
__device__ float  g_logits[(size_t)N_TOK * E_N];    // 128 KB gate logits
__device__ int    g_sync[N_TOK / 128];              // per-row-block completion counters

// ---------------------------------------------------------------- helpers
__device__ __forceinline__ uint32_t smem_u32(const void* p) {
    uint32_t a;
    asm("{ .reg .u64 t; cvta.to.shared.u64 t, %1; cvt.u32.u64 %0, t; }"
        : "=r"(a) : "l"(p));
    return a;
}
__device__ __forceinline__ void cp16(uint32_t dst, const void* src) {
    asm volatile("cp.async.cg.shared.global [%0], [%1], 16;"
                 :: "r"(dst), "l"(src));
}
#define CP_COMMIT() asm volatile("cp.async.commit_group;" ::: "memory")
#define CP_WAIT(n)  asm volatile("cp.async.wait_group %0;" :: "n"(n) : "memory")

__device__ __forceinline__ void ldm_x4(uint32_t& r0, uint32_t& r1,
                                       uint32_t& r2, uint32_t& r3, uint32_t addr) {
    asm volatile("ldmatrix.sync.aligned.m8n8.x4.b16 {%0,%1,%2,%3}, [%4];"
                 : "=r"(r0), "=r"(r1), "=r"(r2), "=r"(r3) : "r"(addr));
}

__device__ __forceinline__ void mma_f16(float& d0, float& d1, float& d2, float& d3,
                                        uint32_t a0, uint32_t a1, uint32_t a2, uint32_t a3,
                                        uint32_t b0, uint32_t b1) {
    asm volatile(
        "mma.sync.aligned.m16n8k16.row.col.f32.f16.f16.f32 "
        "{%0,%1,%2,%3}, {%4,%5,%6,%7}, {%8,%9}, {%0,%1,%2,%3};"
        : "+f"(d0), "+f"(d1), "+f"(d2), "+f"(d3)
        : "r"(a0), "r"(a1), "r"(a2), "r"(a3), "r"(b0), "r"(b1));
}

// ---------------------------------------------------------------- tiling
#define BM   128
#define BN   128
#define BK   64          // halfs per k-tile
#define BKP  72          // padded halfs (144 B rows)
#define SST  3
#define NTHR 256
#define ASTRIDE (BM * BKP)
#define BSTRIDE (BN * BKP)
#define SMEM_BYTES (SST * (ASTRIDE + BSTRIDE) * 2)   // 110592

#define A_OFF(p, m, k) (((p) * BM + (m)) * BKP + (k))
#define B_OFF(p, n, k) (SST * ASTRIDE + ((p) * BN + (n)) * BKP + (k))

// ---------------------------------------------------------------- prep sizes
#define NX4 ((N_TOK * IN_D) / 4)          // 1048576
#define NV4 ((E_N * R_N * IN_D) / 4)      // 32768
#define NZ4 ((N_TOK * E_N) / 4)           // 8192
#define NB_CV ((NX4 + NV4) / 256)         // 4224
#define NB_Z  (NZ4 / 256)                 // 32
#define NB_TR ((HG_N / 32) * (IN_D / 32)) // 256

// weight conversion handled by k_proj bx==3 CTAs
#define NWQ4 ((OUT_D * IN_D) / 4)         // 262144
#define NUQ4 ((E_N * OUT_D * R_N) / 4)    // 32768
#define WCONV_PER_CTA ((NWQ4 + NUQ4) / 32)  // 9216

__global__ void k_prep(const float* __restrict__ x, const float* __restrict__ V,
                       const float* __restrict__ Wg1) {
    int b = blockIdx.x;
    if (b < NB_CV) {
        int i = b * 256 + threadIdx.x;
        const float4* src; __half* dst; int j = i;
        if (j < NX4) { src = (const float4*)x; dst = g_X16; }
        else { j -= NX4; src = (const float4*)V; dst = g_Vr16; }
        float4 v = src[j];
        __half2 h0 = __floats2half2_rn(v.x, v.y);
        __half2 h1 = __floats2half2_rn(v.z, v.w);
        uint2 pk; pk.x = *(uint32_t*)&h0; pk.y = *(uint32_t*)&h1;
        *(uint2*)&dst[(size_t)j * 4] = pk;
    } else if (b < NB_CV + NB_Z) {
        int j = (b - NB_CV) * 256 + threadIdx.x;
        ((float4*)g_logits)[j] = make_float4(0.f, 0.f, 0.f, 0.f);
        if (b == NB_CV && threadIdx.x < N_TOK / 128) g_sync[threadIdx.x] = 0;
    } else {
        __shared__ float t[32][33];
        int tt = b - NB_CV - NB_Z;
        int bx = (tt & 7) * 32;    // hg
        int by = (tt >> 3) * 32;   // in
        int x0 = threadIdx.x & 31, y0 = threadIdx.x >> 5;
#pragma unroll
        for (int r = 0; r < 4; r++) {
            int y = y0 + r * 8;
            t[y][x0] = Wg1[(size_t)(by + y) * HG_N + bx + x0];
        }
        __syncthreads();
#pragma unroll
        for (int r = 0; r < 4; r++) {
            int y = y0 + r * 8;
            g_Wg1T16[(size_t)(bx + y) * IN_D + by + x0] = __float2half_rn(t[x0][y]);
        }
    }
}

// ---------------------------------------------------------------- K1: proj + fused gate
// bx 0,1: h=relu(X@Wg1+bg1) -> logits;  bx 2: T=X@V^T -> g_C;
// bx 3 : convert Wm/U to fp16 (idle-SM CTAs).
// Last finisher per row-block (counter) performs gating and writes g_C16.
__global__ void __launch_bounds__(NTHR, 2) k_proj_mma(
    const float* __restrict__ wm, const float* __restrict__ U,
    const float* __restrict__ bg1, const float* __restrict__ Wg2,
    const float* __restrict__ bg2, const float* __restrict__ S)
{
    const int tid = threadIdx.x;
    const int bx = blockIdx.x;
    const int by = blockIdx.y;

    if (bx == 3) {   // weight-conversion CTAs (run on otherwise-idle SMs)
#pragma unroll 4
        for (int q = 0; q < WCONV_PER_CTA / 256; q++) {
            int g = by * WCONV_PER_CTA + q * 256 + tid;
            const float4* src; __half* dst; int j = g;
            if (j < NWQ4) { src = (const float4*)wm; dst = g_Wmr16; }
            else { j -= NWQ4; src = (const float4*)U; dst = g_Ur16; }
            float4 v = src[j];
            __half2 h0 = __floats2half2_rn(v.x, v.y);
            __half2 h1 = __floats2half2_rn(v.z, v.w);
            uint2 pk; pk.x = *(uint32_t*)&h0; pk.y = *(uint32_t*)&h1;
            *(uint2*)&dst[(size_t)j * 4] = pk;
        }
        return;
    }

    extern __shared__ __half hsm[];
    float* smemf = (float*)hsm;
    const uint32_t sb = smem_u32(hsm);
    const int wid = tid >> 5, lane = tid & 31;
    const int ly = lane >> 2, lx = lane & 3;
    const int row0 = by * BM;
    const int wm_ = (wid & 1) * 64;
    const int wn  = (wid >> 1) * 32;
    const __half* Bsrc = (bx < 2) ? (g_Wg1T16 + (size_t)bx * BN * IN_D) : g_Vr16;

    const int rowA = ((lane >> 3) & 1) * 8 + (lane & 7);
    const int colA = (lane >> 4) * 8;
    const int rowB = ((lane >> 4) & 1) * 8 + (lane & 7);
    const int colB = ((lane >> 3) & 1) * 8;
    const uint32_t aBase = sb + (uint32_t)A_OFF(0, wm_ + rowA, colA) * 2;
    const uint32_t bBase = sb + (uint32_t)B_OFF(0, wn + rowB, colB) * 2;

    float acc[4][4][4];
#pragma unroll
    for (int mt = 0; mt < 4; mt++)
#pragma unroll
        for (int nt = 0; nt < 4; nt++)
#pragma unroll
            for (int r = 0; r < 4; r++) acc[mt][nt][r] = 0.f;

    auto cpAB = [&](int kt) {
        const int p = kt % SST, k0 = kt * BK;
#pragma unroll
        for (int q = 0; q < 4; q++) {
            int u = tid + q * NTHR, m = u >> 3, kc = (u & 7) * 8;
            cp16(sb + (uint32_t)A_OFF(p, m, kc) * 2,
                 g_X16 + (size_t)(row0 + m) * IN_D + k0 + kc);
        }
#pragma unroll
        for (int q = 0; q < 4; q++) {
            int u = tid + q * NTHR, n = u >> 3, kc = (u & 7) * 8;
            cp16(sb + (uint32_t)B_OFF(p, n, kc) * 2,
                 Bsrc + (size_t)n * IN_D + k0 + kc);
        }
        CP_COMMIT();
    };

    const int NT = IN_D / BK;   // 16
    cpAB(0); cpAB(1);
    for (int i = 0; i < NT; i++) {
        const int p = i % SST;
        if (i + 1 < NT) { CP_WAIT(1); } else { CP_WAIT(0); }
        __syncthreads();
        if (i + 2 < NT) cpAB(i + 2);
        const uint32_t aP = aBase + (uint32_t)(p * ASTRIDE) * 2;
        const uint32_t bP = bBase + (uint32_t)(p * BSTRIDE) * 2;
#pragma unroll
        for (int ks = 0; ks < 4; ks++) {
            const int k0 = ks * 16;
            uint32_t af[4][4], bf[4][2];
#pragma unroll
            for (int mt = 0; mt < 4; mt++)
                ldm_x4(af[mt][0], af[mt][1], af[mt][2], af[mt][3],
                       aP + (uint32_t)(mt * 16 * BKP + k0) * 2);
#pragma unroll
            for (int h = 0; h < 2; h++)
                ldm_x4(bf[2*h][0], bf[2*h][1], bf[2*h+1][0], bf[2*h+1][1],
                       bP + (uint32_t)(h * 16 * BKP + k0) * 2);
#pragma unroll
            for (int mt = 0; mt < 4; mt++)
#pragma unroll
                for (int nt = 0; nt < 4; nt++)
                    mma_f16(acc[mt][nt][0], acc[mt][nt][1], acc[mt][nt][2], acc[mt][nt][3],
                            af[mt][0], af[mt][1], af[mt][2], af[mt][3],
                            bf[nt][0], bf[nt][1]);
        }
    }
    __syncthreads();

    if (bx == 2) {
        // write coefficient matrix T (fp32)
#pragma unroll
        for (int mt = 0; mt < 4; mt++) {
            int row = row0 + wm_ + mt * 16 + ly;
#pragma unroll
            for (int nt = 0; nt < 4; nt++) {
                int col = wn + nt * 8 + 2 * lx;
                float2 v0 = {acc[mt][nt][0], acc[mt][nt][1]};
                float2 v1 = {acc[mt][nt][2], acc[mt][nt][3]};
                *(float2*)(g_C + (size_t)row * ER_N + col) = v0;
                *(float2*)(g_C + (size_t)(row + 8) * ER_N + col) = v1;
            }
        }
    } else {
        // gate-logit epilogue (bx = 0,1)
        float* eWg2  = smemf;           // [128][8]
        float* ePart = smemf + 1024;    // [4][128][8]
        {
            int c = tid >> 1, half = tid & 1;
            *(float4*)&eWg2[c * 8 + half * 4] =
                *(const float4*)&Wg2[(size_t)(bx * 128 + c) * E_N + half * 4];
        }
        __syncthreads();

        const int nw = wid >> 1;
        float bgv[4][2];
#pragma unroll
        for (int nt = 0; nt < 4; nt++) {
            int colh = bx * 128 + wn + nt * 8 + 2 * lx;
            bgv[nt][0] = bg1[colh]; bgv[nt][1] = bg1[colh + 1];
        }

#pragma unroll
        for (int mt = 0; mt < 4; mt++) {
            float la0[8], la1[8];
#pragma unroll
            for (int e = 0; e < 8; e++) { la0[e] = 0.f; la1[e] = 0.f; }
#pragma unroll
            for (int nt = 0; nt < 4; nt++) {
                int c0 = wn + nt * 8 + 2 * lx;
                float h00 = fmaxf(acc[mt][nt][0] + bgv[nt][0], 0.f);
                float h01 = fmaxf(acc[mt][nt][1] + bgv[nt][1], 0.f);
                float h10 = fmaxf(acc[mt][nt][2] + bgv[nt][0], 0.f);
                float h11 = fmaxf(acc[mt][nt][3] + bgv[nt][1], 0.f);
                const float* w0 = &eWg2[c0 * 8];
                const float* w1 = &eWg2[(c0 + 1) * 8];
#pragma unroll
                for (int e = 0; e < 8; e++) {
                    la0[e] = fmaf(h00, w0[e], fmaf(h01, w1[e], la0[e]));
                    la1[e] = fmaf(h10, w0[e], fmaf(h11, w1[e], la1[e]));
                }
            }
#pragma unroll
            for (int e = 0; e < 8; e++) {
                la0[e] += __shfl_xor_sync(0xffffffffu, la0[e], 1);
                la0[e] += __shfl_xor_sync(0xffffffffu, la0[e], 2);
                la1[e] += __shfl_xor_sync(0xffffffffu, la1[e], 1);
                la1[e] += __shfl_xor_sync(0xffffffffu, la1[e], 2);
            }
            if (lx == 0) {
                int r0 = wm_ + mt * 16 + ly;
                float* p0 = &ePart[(nw * 128 + r0) * 8];
                float* p1 = &ePart[(nw * 128 + r0 + 8) * 8];
#pragma unroll
                for (int e = 0; e < 8; e += 4) {
                    *(float4*)&p0[e] = make_float4(la0[e], la0[e+1], la0[e+2], la0[e+3]);
                    *(float4*)&p1[e] = make_float4(la1[e], la1[e+1], la1[e+2], la1[e+3]);
                }
            }
        }
        __syncthreads();
#pragma unroll
        for (int k = 0; k < 4; k++) {
            int idx = tid * 4 + k;
            int row = idx >> 3, e = idx & 7;
            float s = ePart[(0 * 128 + row) * 8 + e];
            s += ePart[(1 * 128 + row) * 8 + e];
            s += ePart[(2 * 128 + row) * 8 + e];
            s += ePart[(3 * 128 + row) * 8 + e];
            atomicAdd(&g_logits[(size_t)(row0 + row) * E_N + e], s);
        }
    }

    // ---- completion protocol: last of the 3 GEMM CTAs does the gating ----
    __threadfence();
    __syncthreads();
    __shared__ int s_last;
    if (tid == 0) s_last = (atomicAdd(&g_sync[by], 1) == 2);
    __syncthreads();
    if (!s_last) return;

    // gating for rows row0..row0+127 (one warp per token)
    for (int r = wid; r < BM; r += 8) {
        int n = row0 + r;
        const float4* lp = (const float4*)&g_logits[(size_t)n * E_N];
        float4 l0 = __ldcg(lp), l1 = __ldcg(lp + 1);
        float4 b0 = *(const float4*)&bg2[0];
        float4 b1 = *(const float4*)&bg2[4];
        float acc8[E_N] = {l0.x + b0.x, l0.y + b0.y, l0.z + b0.z, l0.w + b0.w,
                           l1.x + b1.x, l1.y + b1.y, l1.z + b1.z, l1.w + b1.w};

        int i0 = 0; float v0 = acc8[0];
#pragma unroll
        for (int e = 1; e < E_N; e++) if (acc8[e] > v0) { v0 = acc8[e]; i0 = e; }
        int i1 = -1; float v1 = -3.0e38f;
#pragma unroll
        for (int e = 0; e < E_N; e++) if (e != i0 && acc8[e] > v1) { v1 = acc8[e]; i1 = e; }

        float e1 = expf(v1 - v0);
        float ss = 1.f + e1;
        float g0 = 1.f / ss;
        float g1 = e1 / ss;

        __half* c16 = g_C16 + (size_t)n * ER_N;
#pragma unroll
        for (int q = 0; q < 4; q++) {
            int j = lane + q * 32;
            float t = __ldcg(&g_C[(size_t)n * ER_N + j]);
            int e = j >> 4, rr = j & 15;
            float g = (e == i0) ? g0 : ((e == i1) ? g1 : 0.f);
            c16[j] = __float2half_rn(g * S[e * R_N + rr] * t);
        }
    }
}

// ---------------------------------------------------------------- K3: main (fp16, pure async)
__global__ void __launch_bounds__(NTHR, 2) k_main_mma(
    const float* __restrict__ bias, float* __restrict__ out)
{
    extern __shared__ __half hsm[];
    const uint32_t sb = smem_u32(hsm);
    const int tid = threadIdx.x, wid = tid >> 5, lane = tid & 31;
    const int ly = lane >> 2, lx = lane & 3;
    const int row0 = blockIdx.y * BM;
    const int col0 = blockIdx.x * BN;
    const int wm = (wid & 1) * 64;
    const int wn = (wid >> 1) * 32;

    const int rowA = ((lane >> 3) & 1) * 8 + (lane & 7);
    const int colA = (lane >> 4) * 8;
    const int rowB = ((lane >> 4) & 1) * 8 + (lane & 7);
    const int colB = ((lane >> 3) & 1) * 8;
    const uint32_t aBase = sb + (uint32_t)A_OFF(0, wm + rowA, colA) * 2;
    const uint32_t bBase = sb + (uint32_t)B_OFF(0, wn + rowB, colB) * 2;

    float acc[4][4][4];
#pragma unroll
    for (int mt = 0; mt < 4; mt++)
#pragma unroll
        for (int nt = 0; nt < 4; nt++)
#pragma unroll
            for (int r = 0; r < 4; r++) acc[mt][nt][r] = 0.f;

    auto cpAB = [&](int kt) {
        const int p = kt % SST, k0 = kt * BK;
        if (k0 < IN_D) {
#pragma unroll
            for (int q = 0; q < 4; q++) {
                int u = tid + q * NTHR, m = u >> 3, kc = (u & 7) * 8;
                cp16(sb + (uint32_t)A_OFF(p, m, kc) * 2,
                     g_X16 + (size_t)(row0 + m) * IN_D + k0 + kc);
            }
#pragma unroll
            for (int q = 0; q < 4; q++) {
                int u = tid + q * NTHR, n = u >> 3, kc = (u & 7) * 8;
                cp16(sb + (uint32_t)B_OFF(p, n, kc) * 2,
                     g_Wmr16 + (size_t)(col0 + n) * IN_D + k0 + kc);
            }
        } else {
            const int kk = k0 - IN_D;   // 0 or 64
#pragma unroll
            for (int q = 0; q < 4; q++) {
                int u = tid + q * NTHR, m = u >> 3, kc = (u & 7) * 8;
                cp16(sb + (uint32_t)A_OFF(p, m, kc) * 2,
                     g_C16 + (size_t)(row0 + m) * ER_N + kk + kc);
            }
#pragma unroll
            for (int q = 0; q < 4; q++) {
                int u = tid + q * NTHR, n = u >> 3, kc = (u & 7) * 8;
                int kg = kk + kc, e = kg >> 4, r0 = kg & 15;
                cp16(sb + (uint32_t)B_OFF(p, n, kc) * 2,
                     g_Ur16 + ((size_t)e * OUT_D + (col0 + n)) * R_N + r0);
            }
        }
        CP_COMMIT();
    };

    const int NT = (IN_D + ER_N) / BK;   // 18
    cpAB(0); cpAB(1);
    for (int i = 0; i < NT; i++) {
        const int p = i % SST;
        if (i + 1 < NT) { CP_WAIT(1); } else { CP_WAIT(0); }
        __syncthreads();
        if (i + 2 < NT) cpAB(i + 2);
        const uint32_t aP = aBase + (uint32_t)(p * ASTRIDE) * 2;
        const uint32_t bP = bBase + (uint32_t)(p * BSTRIDE) * 2;
#pragma unroll
        for (int ks = 0; ks < 4; ks++) {
            const int k0 = ks * 16;
            uint32_t af[4][4], bf[4][2];
#pragma unroll
            for (int mt = 0; mt < 4; mt++)
                ldm_x4(af[mt][0], af[mt][1], af[mt][2], af[mt][3],
                       aP + (uint32_t)(mt * 16 * BKP + k0) * 2);
#pragma unroll
            for (int h = 0; h < 2; h++)
                ldm_x4(bf[2*h][0], bf[2*h][1], bf[2*h+1][0], bf[2*h+1][1],
                       bP + (uint32_t)(h * 16 * BKP + k0) * 2);
#pragma unroll
            for (int mt = 0; mt < 4; mt++)
#pragma unroll
                for (int nt = 0; nt < 4; nt++)
                    mma_f16(acc[mt][nt][0], acc[mt][nt][1], acc[mt][nt][2], acc[mt][nt][3],
                            af[mt][0], af[mt][1], af[mt][2], af[mt][3],
                            bf[nt][0], bf[nt][1]);
        }
    }

#pragma unroll
    for (int mt = 0; mt < 4; mt++) {
        int row = row0 + wm + mt * 16 + ly;
#pragma unroll
        for (int nt = 0; nt < 4; nt++) {
            int col = col0 + wn + nt * 8 + 2 * lx;
            float b0 = bias[col], b1 = bias[col + 1];
            float2 v0 = {acc[mt][nt][0] + b0, acc[mt][nt][1] + b1};
            float2 v1 = {acc[mt][nt][2] + b0, acc[mt][nt][3] + b1};
            *(float2*)(out + (size_t)row * OUT_D + col) = v0;
            *(float2*)(out + (size_t)(row + 8) * OUT_D + col) = v1;
        }
    }
}

// ---------------------------------------------------------------- launch
extern "C" void kernel_launch(void* const* d_in, const int* in_sizes, int n_in,
                              void* d_out, int out_size)
{
    const float* x    = (const float*)d_in[0];
    const float* wm   = (const float*)d_in[1];
    const float* bias = (const float*)d_in[2];
    const float* U    = (const float*)d_in[3];
    const float* S    = (const float*)d_in[4];
    const float* V    = (const float*)d_in[5];
    const float* Wg1  = (const float*)d_in[6];
    const float* bg1  = (const float*)d_in[7];
    const float* Wg2  = (const float*)d_in[8];
    const float* bg2  = (const float*)d_in[9];
    float* out = (float*)d_out;

    cudaFuncSetAttribute(k_proj_mma, cudaFuncAttributeMaxDynamicSharedMemorySize, SMEM_BYTES);
    cudaFuncSetAttribute(k_main_mma, cudaFuncAttributeMaxDynamicSharedMemorySize, SMEM_BYTES);

    k_prep<<<NB_CV + NB_Z + NB_TR, 256>>>(x, V, Wg1);

    k_proj_mma<<<dim3(4, N_TOK / BM), NTHR, SMEM_BYTES>>>(wm, U, bg1, Wg2, bg2, S);

    k_main_mma<<<dim3(OUT_D / BN, N_TOK / BM), NTHR, SMEM_BYTES>>>(bias, out);
}

// round 16
// speedup vs baseline: 1.2187x; 1.2187x over previous
#include <cuda_runtime.h>
#include <cuda_fp16.h>
#include <cstdint>
#include <math.h>

// ---------------------------------------------------------------- constants
#define N_TOK 4096
#define IN_D  1024
#define OUT_D 1024
#define E_N   8
#define R_N   16
#define HG_N  256
#define ER_N  128

// scratch (no allocation allowed)
__device__ float  g_C[(size_t)N_TOK * ER_N];        // 2 MB coeffs (fp32, k_proj out)
__device__ __half g_C16[(size_t)N_TOK * ER_N];      // 1 MB coeffs fp16 (k_gate out)
__device__ __half g_X16[(size_t)N_TOK * IN_D];      // 8 MB X fp16
__device__ __half g_Wmr16[(size_t)OUT_D * IN_D];    // 2 MB Wm fp16
__device__ __half g_Ur16[(size_t)E_N * OUT_D * R_N];// 256 KB U fp16
__device__ __half g_Vr16[(size_t)E_N * R_N * IN_D]; // 256 KB V fp16
__device__ __half g_Wg1T16[(size_t)HG_N * IN_D];    // 512 KB Wg1^T fp16
__device__ float  g_logits[(size_t)N_TOK * E_N];    // 128 KB gate logits

// ---------------------------------------------------------------- helpers
__device__ __forceinline__ uint32_t smem_u32(const void* p) {
    uint32_t a;
    asm("{ .reg .u64 t; cvta.to.shared.u64 t, %1; cvt.u32.u64 %0, t; }"
        : "=r"(a) : "l"(p));
    return a;
}
__device__ __forceinline__ void cp16(uint32_t dst, const void* src) {
    asm volatile("cp.async.cg.shared.global [%0], [%1], 16;"
                 :: "r"(dst), "l"(src));
}
#define CP_COMMIT() asm volatile("cp.async.commit_group;" ::: "memory")
#define CP_WAIT(n)  asm volatile("cp.async.wait_group %0;" :: "n"(n) : "memory")

__device__ __forceinline__ void ldm_x4(uint32_t& r0, uint32_t& r1,
                                       uint32_t& r2, uint32_t& r3, uint32_t addr) {
    asm volatile("ldmatrix.sync.aligned.m8n8.x4.b16 {%0,%1,%2,%3}, [%4];"
                 : "=r"(r0), "=r"(r1), "=r"(r2), "=r"(r3) : "r"(addr));
}

__device__ __forceinline__ void mma_f16(float& d0, float& d1, float& d2, float& d3,
                                        uint32_t a0, uint32_t a1, uint32_t a2, uint32_t a3,
                                        uint32_t b0, uint32_t b1) {
    asm volatile(
        "mma.sync.aligned.m16n8k16.row.col.f32.f16.f16.f32 "
        "{%0,%1,%2,%3}, {%4,%5,%6,%7}, {%8,%9}, {%0,%1,%2,%3};"
        : "+f"(d0), "+f"(d1), "+f"(d2), "+f"(d3)
        : "r"(a0), "r"(a1), "r"(a2), "r"(a3), "r"(b0), "r"(b1));
}

// ---------------------------------------------------------------- tiling
#define BM   128
#define BN   128
#define BK   64          // halfs per k-tile (128 B rows)
#define BKP  72          // padded halfs (144 B rows)
#define SST  3
#define NTHR 256
#define ASTRIDE (BM * BKP)            // halfs
#define BSTRIDE (BN * BKP)
#define SMEM_BYTES (SST * (ASTRIDE + BSTRIDE) * 2)   // 110592

#define A_OFF(p, m, k) (((p) * BM + (m)) * BKP + (k))   // half units
#define B_OFF(p, n, k) (SST * ASTRIDE + ((p) * BN + (n)) * BKP + (k))

// ---------------------------------------------------------------- prep (one launch)
#define NX4 ((N_TOK * IN_D) / 4)
#define NW4 ((OUT_D * IN_D) / 4)
#define NU4 ((E_N * OUT_D * R_N) / 4)
#define NV4 ((E_N * R_N * IN_D) / 4)
#define NZ4 ((N_TOK * E_N) / 4)
#define NCV4 (NX4 + NW4 + NU4 + NV4)            // 1376256
#define NB_CV (NCV4 / (256 * 4))                // 1344 (4 float4 per thread)
#define NB_Z  (NZ4 / 256)                        // 32
#define NB_TR ((HG_N / 32) * (IN_D / 32))        // 256

__global__ void k_prep(const float* __restrict__ x, const float* __restrict__ wm,
                       const float* __restrict__ U, const float* __restrict__ V,
                       const float* __restrict__ Wg1) {
    int b = blockIdx.x;
    if (b < NB_CV) {
        // 4 independent float4 conversions per thread (MLP>=4 hides DRAM latency)
        int base = b * 1024 + threadIdx.x;     // stride 256 between the 4
#pragma unroll
        for (int q = 0; q < 4; q++) {
            int i = base + q * 256;
            const float4* src; __half* dst; int j = i;
            if (j < NX4)               { src = (const float4*)x;  dst = g_X16; }
            else if ((j -= NX4) < NW4) { src = (const float4*)wm; dst = g_Wmr16; }
            else if ((j -= NW4) < NU4) { src = (const float4*)U;  dst = g_Ur16; }
            else { j -= NU4;             src = (const float4*)V;  dst = g_Vr16; }
            float4 v = src[j];
            __half2 h0 = __floats2half2_rn(v.x, v.y);
            __half2 h1 = __floats2half2_rn(v.z, v.w);
            uint2 pk;
            pk.x = *(uint32_t*)&h0; pk.y = *(uint32_t*)&h1;
            *(uint2*)&dst[(size_t)j * 4] = pk;
        }
    } else if (b < NB_CV + NB_Z) {
        int j = (b - NB_CV) * 256 + threadIdx.x;
        ((float4*)g_logits)[j] = make_float4(0.f, 0.f, 0.f, 0.f);
    } else {
        __shared__ float t[32][33];
        int tt = b - NB_CV - NB_Z;
        int bx = (tt & 7) * 32;    // hg
        int by = (tt >> 3) * 32;   // in
        int x0 = threadIdx.x & 31, y0 = threadIdx.x >> 5;
#pragma unroll
        for (int r = 0; r < 4; r++) {
            int y = y0 + r * 8;
            t[y][x0] = Wg1[(size_t)(by + y) * HG_N + bx + x0];
        }
        __syncthreads();
#pragma unroll
        for (int r = 0; r < 4; r++) {
            int y = y0 + r * 8;
            g_Wg1T16[(size_t)(bx + y) * IN_D + by + x0] = __float2half_rn(t[x0][y]);
        }
    }
}

// ---------------------------------------------------------------- K1: proj (fp16)
// bx 0,1: h = relu(X@Wg1+bg1) -> partial logits; bx 2: T = X@V^T -> g_C (fp32)
__global__ void __launch_bounds__(NTHR, 2) k_proj_mma(
    const float* __restrict__ bg1, const float* __restrict__ Wg2)
{
    extern __shared__ __half hsm[];
    float* smemf = (float*)hsm;
    const uint32_t sb = smem_u32(hsm);
    const int tid = threadIdx.x, wid = tid >> 5, lane = tid & 31;
    const int ly = lane >> 2, lx = lane & 3;
    const int bx = blockIdx.x;
    const int row0 = blockIdx.y * BM;
    const int wm = (wid & 1) * 64;
    const int wn = (wid >> 1) * 32;
    const __half* Bsrc = (bx < 2) ? (g_Wg1T16 + (size_t)bx * BN * IN_D) : g_Vr16;

    const int rowA = ((lane >> 3) & 1) * 8 + (lane & 7);
    const int colA = (lane >> 4) * 8;                 // halfs
    const int rowB = ((lane >> 4) & 1) * 8 + (lane & 7);
    const int colB = ((lane >> 3) & 1) * 8;           // halfs
    const uint32_t aBase = sb + (uint32_t)A_OFF(0, wm + rowA, colA) * 2;
    const uint32_t bBase = sb + (uint32_t)B_OFF(0, wn + rowB, colB) * 2;

    float acc[4][4][4];
#pragma unroll
    for (int mt = 0; mt < 4; mt++)
#pragma unroll
        for (int nt = 0; nt < 4; nt++)
#pragma unroll
            for (int r = 0; r < 4; r++) acc[mt][nt][r] = 0.f;

    auto cpAB = [&](int kt) {
        const int p = kt % SST, k0 = kt * BK;
#pragma unroll
        for (int q = 0; q < 4; q++) {
            int u = tid + q * NTHR, m = u >> 3, kc = (u & 7) * 8;
            cp16(sb + (uint32_t)A_OFF(p, m, kc) * 2,
                 g_X16 + (size_t)(row0 + m) * IN_D + k0 + kc);
        }
#pragma unroll
        for (int q = 0; q < 4; q++) {
            int u = tid + q * NTHR, n = u >> 3, kc = (u & 7) * 8;
            cp16(sb + (uint32_t)B_OFF(p, n, kc) * 2,
                 Bsrc + (size_t)n * IN_D + k0 + kc);
        }
        CP_COMMIT();
    };

    const int NT = IN_D / BK;   // 16
    cpAB(0); cpAB(1);
    for (int i = 0; i < NT; i++) {
        const int p = i % SST;
        if (i + 1 < NT) { CP_WAIT(1); } else { CP_WAIT(0); }
        __syncthreads();
        if (i + 2 < NT) cpAB(i + 2);
        const uint32_t aP = aBase + (uint32_t)(p * ASTRIDE) * 2;
        const uint32_t bP = bBase + (uint32_t)(p * BSTRIDE) * 2;
#pragma unroll
        for (int ks = 0; ks < 4; ks++) {
            const int k0 = ks * 16;   // halfs
            uint32_t af[4][4], bf[4][2];
#pragma unroll
            for (int mt = 0; mt < 4; mt++)
                ldm_x4(af[mt][0], af[mt][1], af[mt][2], af[mt][3],
                       aP + (uint32_t)(mt * 16 * BKP + k0) * 2);
#pragma unroll
            for (int h = 0; h < 2; h++)
                ldm_x4(bf[2*h][0], bf[2*h][1], bf[2*h+1][0], bf[2*h+1][1],
                       bP + (uint32_t)(h * 16 * BKP + k0) * 2);
#pragma unroll
            for (int mt = 0; mt < 4; mt++)
#pragma unroll
                for (int nt = 0; nt < 4; nt++)
                    mma_f16(acc[mt][nt][0], acc[mt][nt][1], acc[mt][nt][2], acc[mt][nt][3],
                            af[mt][0], af[mt][1], af[mt][2], af[mt][3],
                            bf[nt][0], bf[nt][1]);
        }
    }
    __syncthreads();

    if (bx == 2) {
#pragma unroll
        for (int mt = 0; mt < 4; mt++) {
            int row = row0 + wm + mt * 16 + ly;
#pragma unroll
            for (int nt = 0; nt < 4; nt++) {
                int col = wn + nt * 8 + 2 * lx;
                float2 v0 = {acc[mt][nt][0], acc[mt][nt][1]};
                float2 v1 = {acc[mt][nt][2], acc[mt][nt][3]};
                *(float2*)(g_C + (size_t)row * ER_N + col) = v0;
                *(float2*)(g_C + (size_t)(row + 8) * ER_N + col) = v1;
            }
        }
        return;
    }

    // gate-logit epilogue (bx = 0,1)
    float* eWg2  = smemf;           // [128][8]
    float* ePart = smemf + 1024;    // [4][128][8]
    {
        int c = tid >> 1, half = tid & 1;
        *(float4*)&eWg2[c * 8 + half * 4] =
            *(const float4*)&Wg2[(size_t)(bx * 128 + c) * E_N + half * 4];
    }
    __syncthreads();

    const int nw = wid >> 1;
    float bgv[4][2];
#pragma unroll
    for (int nt = 0; nt < 4; nt++) {
        int colh = bx * 128 + wn + nt * 8 + 2 * lx;
        bgv[nt][0] = bg1[colh]; bgv[nt][1] = bg1[colh + 1];
    }

#pragma unroll
    for (int mt = 0; mt < 4; mt++) {
        float la0[8], la1[8];
#pragma unroll
        for (int e = 0; e < 8; e++) { la0[e] = 0.f; la1[e] = 0.f; }
#pragma unroll
        for (int nt = 0; nt < 4; nt++) {
            int c0 = wn + nt * 8 + 2 * lx;
            float h00 = fmaxf(acc[mt][nt][0] + bgv[nt][0], 0.f);
            float h01 = fmaxf(acc[mt][nt][1] + bgv[nt][1], 0.f);
            float h10 = fmaxf(acc[mt][nt][2] + bgv[nt][0], 0.f);
            float h11 = fmaxf(acc[mt][nt][3] + bgv[nt][1], 0.f);
            const float* w0 = &eWg2[c0 * 8];
            const float* w1 = &eWg2[(c0 + 1) * 8];
#pragma unroll
            for (int e = 0; e < 8; e++) {
                la0[e] = fmaf(h00, w0[e], fmaf(h01, w1[e], la0[e]));
                la1[e] = fmaf(h10, w0[e], fmaf(h11, w1[e], la1[e]));
            }
        }
#pragma unroll
        for (int e = 0; e < 8; e++) {
            la0[e] += __shfl_xor_sync(0xffffffffu, la0[e], 1);
            la0[e] += __shfl_xor_sync(0xffffffffu, la0[e], 2);
            la1[e] += __shfl_xor_sync(0xffffffffu, la1[e], 1);
            la1[e] += __shfl_xor_sync(0xffffffffu, la1[e], 2);
        }
        if (lx == 0) {
            int r0 = wm + mt * 16 + ly;
            float* p0 = &ePart[(nw * 128 + r0) * 8];
            float* p1 = &ePart[(nw * 128 + r0 + 8) * 8];
#pragma unroll
            for (int e = 0; e < 8; e += 4) {
                *(float4*)&p0[e] = make_float4(la0[e], la0[e+1], la0[e+2], la0[e+3]);
                *(float4*)&p1[e] = make_float4(la1[e], la1[e+1], la1[e+2], la1[e+3]);
            }
        }
    }
    __syncthreads();
#pragma unroll
    for (int k = 0; k < 4; k++) {
        int idx = tid * 4 + k;
        int row = idx >> 3, e = idx & 7;
        float s = ePart[(0 * 128 + row) * 8 + e];
        s += ePart[(1 * 128 + row) * 8 + e];
        s += ePart[(2 * 128 + row) * 8 + e];
        s += ePart[(3 * 128 + row) * 8 + e];
        atomicAdd(&g_logits[(size_t)(row0 + row) * E_N + e], s);
    }
}

// ---------------------------------------------------------------- K2: gate (slim)
__global__ void __launch_bounds__(256) k_gate(
    const float* __restrict__ bg2, const float* __restrict__ S)
{
    const int warp = threadIdx.x >> 5;
    const int lane = threadIdx.x & 31;
    const int n = blockIdx.x * 8 + warp;
    if (n >= N_TOK) return;

    float4 l0 = *(const float4*)&g_logits[(size_t)n * E_N];
    float4 l1 = *(const float4*)&g_logits[(size_t)n * E_N + 4];
    float4 b0 = *(const float4*)&bg2[0];
    float4 b1 = *(const float4*)&bg2[4];
    float acc[E_N] = {l0.x + b0.x, l0.y + b0.y, l0.z + b0.z, l0.w + b0.w,
                      l1.x + b1.x, l1.y + b1.y, l1.z + b1.z, l1.w + b1.w};

    int i0 = 0; float v0 = acc[0];
#pragma unroll
    for (int e = 1; e < E_N; e++) if (acc[e] > v0) { v0 = acc[e]; i0 = e; }
    int i1 = -1; float v1 = -3.0e38f;
#pragma unroll
    for (int e = 0; e < E_N; e++) if (e != i0 && acc[e] > v1) { v1 = acc[e]; i1 = e; }

    float e1 = expf(v1 - v0);
    float s  = 1.f + e1;
    float g0 = 1.f / s;
    float g1 = e1 / s;

    const float* c = g_C + (size_t)n * ER_N;
    __half* c16 = g_C16 + (size_t)n * ER_N;
#pragma unroll
    for (int q = 0; q < 4; q++) {
        int j = lane + q * 32;
        float t = c[j];
        int e = j >> 4, r = j & 15;
        float g = (e == i0) ? g0 : ((e == i1) ? g1 : 0.f);
        c16[j] = __float2half_rn(g * S[e * R_N + r] * t);
    }
}

// ---------------------------------------------------------------- K3: main (fp16, pure async)
// out = X@Wm^T + Call@Uf + bias   (K = 1024 + 128 = 1152, BK=64 -> 18 iters)
__global__ void __launch_bounds__(NTHR, 2) k_main_mma(
    const float* __restrict__ bias, float* __restrict__ out)
{
    extern __shared__ __half hsm[];
    const uint32_t sb = smem_u32(hsm);
    const int tid = threadIdx.x, wid = tid >> 5, lane = tid & 31;
    const int ly = lane >> 2, lx = lane & 3;
    const int row0 = blockIdx.y * BM;
    const int col0 = blockIdx.x * BN;
    const int wm = (wid & 1) * 64;
    const int wn = (wid >> 1) * 32;

    const int rowA = ((lane >> 3) & 1) * 8 + (lane & 7);
    const int colA = (lane >> 4) * 8;
    const int rowB = ((lane >> 4) & 1) * 8 + (lane & 7);
    const int colB = ((lane >> 3) & 1) * 8;
    const uint32_t aBase = sb + (uint32_t)A_OFF(0, wm + rowA, colA) * 2;
    const uint32_t bBase = sb + (uint32_t)B_OFF(0, wn + rowB, colB) * 2;

    float acc[4][4][4];
#pragma unroll
    for (int mt = 0; mt < 4; mt++)
#pragma unroll
        for (int nt = 0; nt < 4; nt++)
#pragma unroll
            for (int r = 0; r < 4; r++) acc[mt][nt][r] = 0.f;

    auto cpAB = [&](int kt) {
        const int p = kt % SST, k0 = kt * BK;
        if (k0 < IN_D) {
#pragma unroll
            for (int q = 0; q < 4; q++) {
                int u = tid + q * NTHR, m = u >> 3, kc = (u & 7) * 8;
                cp16(sb + (uint32_t)A_OFF(p, m, kc) * 2,
                     g_X16 + (size_t)(row0 + m) * IN_D + k0 + kc);
            }
#pragma unroll
            for (int q = 0; q < 4; q++) {
                int u = tid + q * NTHR, n = u >> 3, kc = (u & 7) * 8;
                cp16(sb + (uint32_t)B_OFF(p, n, kc) * 2,
                     g_Wmr16 + (size_t)(col0 + n) * IN_D + k0 + kc);
            }
        } else {
            const int kk = k0 - IN_D;   // 0 or 64
#pragma unroll
            for (int q = 0; q < 4; q++) {
                int u = tid + q * NTHR, m = u >> 3, kc = (u & 7) * 8;
                cp16(sb + (uint32_t)A_OFF(p, m, kc) * 2,
                     g_C16 + (size_t)(row0 + m) * ER_N + kk + kc);
            }
#pragma unroll
            for (int q = 0; q < 4; q++) {
                int u = tid + q * NTHR, n = u >> 3, kc = (u & 7) * 8;
                int kg = kk + kc, e = kg >> 4, r0 = kg & 15;
                cp16(sb + (uint32_t)B_OFF(p, n, kc) * 2,
                     g_Ur16 + ((size_t)e * OUT_D + (col0 + n)) * R_N + r0);
            }
        }
        CP_COMMIT();
    };

    const int NT = (IN_D + ER_N) / BK;   // 18
    cpAB(0); cpAB(1);
    for (int i = 0; i < NT; i++) {
        const int p = i % SST;
        if (i + 1 < NT) { CP_WAIT(1); } else { CP_WAIT(0); }
        __syncthreads();
        if (i + 2 < NT) cpAB(i + 2);
        const uint32_t aP = aBase + (uint32_t)(p * ASTRIDE) * 2;
        const uint32_t bP = bBase + (uint32_t)(p * BSTRIDE) * 2;
#pragma unroll
        for (int ks = 0; ks < 4; ks++) {
            const int k0 = ks * 16;
            uint32_t af[4][4], bf[4][2];
#pragma unroll
            for (int mt = 0; mt < 4; mt++)
                ldm_x4(af[mt][0], af[mt][1], af[mt][2], af[mt][3],
                       aP + (uint32_t)(mt * 16 * BKP + k0) * 2);
#pragma unroll
            for (int h = 0; h < 2; h++)
                ldm_x4(bf[2*h][0], bf[2*h][1], bf[2*h+1][0], bf[2*h+1][1],
                       bP + (uint32_t)(h * 16 * BKP + k0) * 2);
#pragma unroll
            for (int mt = 0; mt < 4; mt++)
#pragma unroll
                for (int nt = 0; nt < 4; nt++)
                    mma_f16(acc[mt][nt][0], acc[mt][nt][1], acc[mt][nt][2], acc[mt][nt][3],
                            af[mt][0], af[mt][1], af[mt][2], af[mt][3],
                            bf[nt][0], bf[nt][1]);
        }
    }

#pragma unroll
    for (int mt = 0; mt < 4; mt++) {
        int row = row0 + wm + mt * 16 + ly;
#pragma unroll
        for (int nt = 0; nt < 4; nt++) {
            int col = col0 + wn + nt * 8 + 2 * lx;
            float b0 = bias[col], b1 = bias[col + 1];
            float2 v0 = {acc[mt][nt][0] + b0, acc[mt][nt][1] + b1};
            float2 v1 = {acc[mt][nt][2] + b0, acc[mt][nt][3] + b1};
            *(float2*)(out + (size_t)row * OUT_D + col) = v0;
            *(float2*)(out + (size_t)(row + 8) * OUT_D + col) = v1;
        }
    }
}

// ---------------------------------------------------------------- launch
extern "C" void kernel_launch(void* const* d_in, const int* in_sizes, int n_in,
                              void* d_out, int out_size)
{
    const float* x    = (const float*)d_in[0];
    const float* wm   = (const float*)d_in[1];
    const float* bias = (const float*)d_in[2];
    const float* U    = (const float*)d_in[3];
    const float* S    = (const float*)d_in[4];
    const float* V    = (const float*)d_in[5];
    const float* Wg1  = (const float*)d_in[6];
    const float* bg1  = (const float*)d_in[7];
    const float* Wg2  = (const float*)d_in[8];
    const float* bg2  = (const float*)d_in[9];
    float* out = (float*)d_out;

    cudaFuncSetAttribute(k_proj_mma, cudaFuncAttributeMaxDynamicSharedMemorySize, SMEM_BYTES);
    cudaFuncSetAttribute(k_main_mma, cudaFuncAttributeMaxDynamicSharedMemorySize, SMEM_BYTES);

    k_prep<<<NB_CV + NB_Z + NB_TR, 256>>>(x, wm, U, V, Wg1);

    k_proj_mma<<<dim3(3, N_TOK / BM), NTHR, SMEM_BYTES>>>(bg1, Wg2);

    k_gate<<<N_TOK / 8, 256>>>(bg2, S);

    k_main_mma<<<dim3(OUT_D / BN, N_TOK / BM), NTHR, SMEM_BYTES>>>(bias, out);
}